// round 10
// baseline (speedup 1.0000x reference)
#include <cuda_runtime.h>
#include <cuda_bf16.h>
#include <cstdint>

#define HDIM 20
#define TPB 32   // 8 groups of 4 lanes per warp; group handles 2 elements

typedef unsigned long long u64;

union F2u { float2 f; u64 u; };
union F4u { float4 f; u64 u[2]; };

__device__ __forceinline__ u64 pack2(float lo, float hi) {
    F2u t; t.f = make_float2(lo, hi); return t.u;
}
__device__ __forceinline__ float lo2(u64 a) { F2u t; t.u = a; return t.f.x; }
__device__ __forceinline__ float hi2(u64 a) { F2u t; t.u = a; return t.f.y; }

__device__ __forceinline__ u64 fma2(u64 a, u64 b, u64 c) {
    u64 d;
    asm("fma.rn.f32x2 %0, %1, %2, %3;" : "=l"(d) : "l"(a), "l"(b), "l"(c));
    return d;
}
__device__ __forceinline__ u64 mul2(u64 a, u64 b) {
    u64 d;
    asm("mul.rn.f32x2 %0, %1, %2;" : "=l"(d) : "l"(a), "l"(b));
    return d;
}
__device__ __forceinline__ u64 add2(u64 a, u64 b) {
    u64 d;
    asm("add.rn.f32x2 %0, %1, %2;" : "=l"(d) : "l"(a), "l"(b));
    return d;
}
__device__ __forceinline__ float ex2f(float x) {
    float y; asm("ex2.approx.f32 %0, %1;" : "=f"(y) : "f"(x)); return y;
}
__device__ __forceinline__ float rcpf(float x) {
    float y; asm("rcp.approx.f32 %0, %1;" : "=f"(y) : "f"(x)); return y;
}
__device__ __forceinline__ u64 ex2x2(u64 a) { return pack2(ex2f(lo2(a)), ex2f(hi2(a))); }
__device__ __forceinline__ u64 rcp2(u64 a)  { return pack2(rcpf(lo2(a)), rcpf(hi2(a))); }

// pre-scales: sigmoid(v) = rcp(1 + ex2(C1*v)), tanh(v) = 2*rcp(1 + ex2(C2*v)) - 1
#define C1 (-1.4426950408889634f)
#define C2 (-2.8853900817779268f)
#define SIGN2 0x8000000080000000ULL

__global__ __launch_bounds__(TPB, 14)   // cap regs ~146 so all 2048 warps are resident
void gru_decoder_kernel(const float* __restrict__ hidden,
                        const float* __restrict__ w_ih,
                        const float* __restrict__ w_hh,
                        const float* __restrict__ b_ih,
                        const float* __restrict__ b_hh,
                        const float* __restrict__ w_l,
                        const float* __restrict__ b_l,
                        float* __restrict__ out,
                        int B, int step)
{
    // Extended W[i][j]: j<20 -> w_hh[i*20+j], j=20,21 -> w_ih[i*2+(j-20)]
    // WQ[p][jj][12]: p = gate pair, jj = column pair (jj=10 -> x columns):
    //   c0..3  = C1*{W[2p][j0],    W[2p][j1],    W[2p+1][j0],  W[2p+1][j1]}   (r)
    //   c4..7  = C1*{W[20+2p][j0], W[20+2p][j1], W[21+2p][j0], W[21+2p][j1]}  (z)
    //   c8..11 = C2*{W[40+2p][j0], W[40+2p][j1], W[41+2p][j0], W[41+2p][j1]}  (n)
    __shared__ __align__(16) float WQ[10][11][12];
    __shared__ __align__(16) float BQ[10][8];   // {br0,br1,bz0,bz1, bhn0,bhn1,bin0,bin1}
    __shared__ __align__(16) float WLY[10][4];  // {wl0_j0, wl0_j1, wl1_j0, wl1_j1}
    __shared__ float BL2[2];

    const int tid = threadIdx.x;

    for (int idx = tid; idx < 10 * 11 * 12; idx += TPB) {
        int p  = idx / 132;
        int r  = idx % 132;
        int jj = r / 12;
        int c  = r % 12;
        int g  = c >> 2;            // 0=r, 1=z, 2=n
        int s  = c & 3;             // bit1 = row offset, bit0 = col offset
        int row = ((g == 0) ? 2*p : (g == 1) ? 20 + 2*p : 40 + 2*p) + (s >> 1);
        int j   = ((jj < 10) ? 2*jj : 20) + (s & 1);
        float w = (j < 20) ? w_hh[row * 20 + j] : w_ih[row * 2 + (j - 20)];
        WQ[p][jj][c] = w * ((g == 2) ? C2 : C1);
    }
    if (tid < 10) {
        int p = tid;
        BQ[p][0] = C1 * (b_ih[2*p]      + b_hh[2*p]);
        BQ[p][1] = C1 * (b_ih[2*p + 1]  + b_hh[2*p + 1]);
        BQ[p][2] = C1 * (b_ih[20 + 2*p] + b_hh[20 + 2*p]);
        BQ[p][3] = C1 * (b_ih[21 + 2*p] + b_hh[21 + 2*p]);
        BQ[p][4] = C2 * b_hh[40 + 2*p];
        BQ[p][5] = C2 * b_hh[41 + 2*p];
        BQ[p][6] = C2 * b_ih[40 + 2*p];
        BQ[p][7] = C2 * b_ih[41 + 2*p];
        WLY[p][0] = w_l[2*p];
        WLY[p][1] = w_l[2*p + 1];
        WLY[p][2] = w_l[20 + 2*p];
        WLY[p][3] = w_l[21 + 2*p];
    }
    if (tid < 2) BL2[tid] = b_l[tid];
    __syncthreads();

    const int gtid = blockIdx.x * TPB + tid;
    const int sub  = gtid & 3;                 // role within 4-lane group
    const int gid  = gtid >> 2;                // group id
    const int e0   = gid * 2;                  // group handles elements e0, e0+1
    if (e0 >= B) return;
    const int odd  = sub & 1;                  // odd subs own 2 pairs, even own 3
    const int hig  = (sub >> 1) & 1;           // high subs own pairs 5..9 range
    const int pbase = hig * 5 + odd * 3;       // sub->pbase: 0,3,5,8
    const int np    = 3 - odd;                 // pairs owned: 3,2,3,2

    // register caches for own pairs (clamped index keeps smem reads in-bounds)
    F4u XRc[3], XZc[3], XNc[3], WLc[3];
#pragma unroll
    for (int q = 0; q < 3; ++q) {
        const int pc = (pbase + q > 9) ? 9 : (pbase + q);
        XRc[q].f = *(const float4*)(&WQ[pc][10][0]);
        XZc[q].f = *(const float4*)(&WQ[pc][10][4]);
        XNc[q].f = *(const float4*)(&WQ[pc][10][8]);
        WLc[q].f = *(const float4*)(&WLY[pc][0]);
    }
    if (odd) { WLc[2].u[0] = 0; WLc[2].u[1] = 0; }   // 3rd pair unused for odd subs
    u64 blu;
    { F2u t; t.f = make_float2(BL2[0], BL2[1]); blu = t.u; }

    // h state (full, both elements): hp[e][jj] = (h[2jj], h[2jj+1])
    u64 hp[2][10];
#pragma unroll
    for (int e2 = 0; e2 < 2; ++e2) {
        const float4* hsrc = (const float4*)(hidden + (size_t)(e0 + e2) * HDIM);
#pragma unroll
        for (int q = 0; q < 5; ++q) {
            float4 v = hsrc[q];
            hp[e2][2*q]     = pack2(v.x, v.y);
            hp[e2][2*q + 1] = pack2(v.z, v.w);
        }
    }

    const u64 ONE2 = pack2(1.0f, 1.0f);
    const u64 TWO2 = pack2(2.0f, 2.0f);
    const u64 NEG1 = pack2(-1.0f, -1.0f);

    u64 xp[2] = {0, 0};
    float* outb0 = out + (size_t)e0 * step * 2;
    float* outb1 = out + (size_t)(e0 + 1) * step * 2;

#pragma unroll 1
    for (int t = 0; t < step; ++t) {
        u64 hn_new[2][3];
        hn_new[0][2] = 0; hn_new[1][2] = 0;    // keep exchange/y math finite for odd subs

#pragma unroll
        for (int q = 0; q < 3; ++q) {
            if (q < np) {
                const float* wq = &WQ[pbase + q][0][0];

                u64 Ar0[2], Ar1[2], Az0[2], Az1[2], An0[2], An1[2];
                {
                    F4u R, Z, Nw;
                    R.f  = *(const float4*)(wq + 0);
                    Z.f  = *(const float4*)(wq + 4);
                    Nw.f = *(const float4*)(wq + 8);
#pragma unroll
                    for (int e2 = 0; e2 < 2; ++e2) {
                        const u64 h0 = hp[e2][0];
                        Ar0[e2] = mul2(R.u[0],  h0);
                        Ar1[e2] = mul2(R.u[1],  h0);
                        Az0[e2] = mul2(Z.u[0],  h0);
                        Az1[e2] = mul2(Z.u[1],  h0);
                        An0[e2] = mul2(Nw.u[0], h0);
                        An1[e2] = mul2(Nw.u[1], h0);
                    }
                }
#pragma unroll
                for (int jj = 1; jj < 10; ++jj) {
                    F4u R, Z, Nw;
                    R.f  = *(const float4*)(wq + jj * 12);
                    Z.f  = *(const float4*)(wq + jj * 12 + 4);
                    Nw.f = *(const float4*)(wq + jj * 12 + 8);
#pragma unroll
                    for (int e2 = 0; e2 < 2; ++e2) {
                        const u64 hj = hp[e2][jj];
                        Ar0[e2] = fma2(R.u[0],  hj, Ar0[e2]);
                        Ar1[e2] = fma2(R.u[1],  hj, Ar1[e2]);
                        Az0[e2] = fma2(Z.u[0],  hj, Az0[e2]);
                        Az1[e2] = fma2(Z.u[1],  hj, Az1[e2]);
                        An0[e2] = fma2(Nw.u[0], hj, An0[e2]);
                        An1[e2] = fma2(Nw.u[1], hj, An1[e2]);
                    }
                }

                // x slot (register-cached weights); n's x part separate (inn)
                u64 In0[2], In1[2];
#pragma unroll
                for (int e2 = 0; e2 < 2; ++e2) {
                    const u64 xv = xp[e2];
                    Ar0[e2] = fma2(XRc[q].u[0], xv, Ar0[e2]);
                    Ar1[e2] = fma2(XRc[q].u[1], xv, Ar1[e2]);
                    Az0[e2] = fma2(XZc[q].u[0], xv, Az0[e2]);
                    Az1[e2] = fma2(XZc[q].u[1], xv, Az1[e2]);
                    In0[e2] = mul2(XNc[q].u[0], xv);
                    In1[e2] = mul2(XNc[q].u[1], xv);
                }

                // biases from smem (cheap, avoids register pressure)
                F4u Brz, Bn;
                Brz.f = *(const float4*)(&BQ[pbase + q][0]);
                Bn.f  = *(const float4*)(&BQ[pbase + q][4]);

#pragma unroll
                for (int e2 = 0; e2 < 2; ++e2) {
                    const u64 rArg = add2(pack2(lo2(Ar0[e2]) + hi2(Ar0[e2]),
                                                lo2(Ar1[e2]) + hi2(Ar1[e2])), Brz.u[0]);
                    const u64 zArg = add2(pack2(lo2(Az0[e2]) + hi2(Az0[e2]),
                                                lo2(Az1[e2]) + hi2(Az1[e2])), Brz.u[1]);
                    const u64 hnv  = add2(pack2(lo2(An0[e2]) + hi2(An0[e2]),
                                                lo2(An1[e2]) + hi2(An1[e2])), Bn.u[0]);
                    const u64 innv = add2(pack2(lo2(In0[e2]) + hi2(In0[e2]),
                                                lo2(In1[e2]) + hi2(In1[e2])), Bn.u[1]);

                    const u64 rv = rcp2(add2(ex2x2(rArg), ONE2));
                    const u64 zv = rcp2(add2(ex2x2(zArg), ONE2));
                    const u64 s  = fma2(rv, hnv, innv);
                    const u64 nv = fma2(TWO2, rcp2(add2(ex2x2(s), ONE2)), NEG1);

                    const u64 hold = hp[e2][pbase + q];
                    const u64 t1 = fma2(zv, hold, nv);            // z*h + n
                    hn_new[e2][q] = fma2(zv ^ SIGN2, nv, t1);     // (z*h+n) - z*n
                }
            }
        }

        // ---- y partial over own pairs, butterfly-reduced across the 4 lanes ----
        u64 yfin[2];
#pragma unroll
        for (int e2 = 0; e2 < 2; ++e2) {
            u64 Y0 = mul2(WLc[0].u[0], hn_new[e2][0]);
            u64 Y1 = mul2(WLc[0].u[1], hn_new[e2][0]);
            Y0 = fma2(WLc[1].u[0], hn_new[e2][1], Y0);
            Y1 = fma2(WLc[1].u[1], hn_new[e2][1], Y1);
            Y0 = fma2(WLc[2].u[0], hn_new[e2][2], Y0);    // zero-weight for odd subs
            Y1 = fma2(WLc[2].u[1], hn_new[e2][2], Y1);
            u64 ym = pack2(lo2(Y0) + hi2(Y0), lo2(Y1) + hi2(Y1));
            ym = add2(ym, __shfl_xor_sync(0xFFFFFFFFu, ym, 1));
            ym = add2(ym, __shfl_xor_sync(0xFFFFFFFFu, ym, 2));
            yfin[e2] = add2(ym, blu);
        }

        // ---- h exchange: 2-stage butterfly broadcast of all 10 pairs ----
#pragma unroll
        for (int e2 = 0; e2 < 2; ++e2) {
            const u64 s0 = hn_new[e2][0];
            const u64 s1 = hn_new[e2][1];
            const u64 s2 = hn_new[e2][2];
            const u64 r0 = __shfl_xor_sync(0xFFFFFFFFu, s0, 1);
            const u64 r1 = __shfl_xor_sync(0xFFFFFFFFu, s1, 1);
            const u64 r2 = __shfl_xor_sync(0xFFFFFFFFu, s2, 1);
            // assemble own half (pairs 0-4 for subs 0,1; pairs 5-9 for subs 2,3)
            u64 h0 = odd ? r0 : s0;
            u64 h1 = odd ? r1 : s1;
            u64 h2 = odd ? r2 : s2;
            u64 h3 = odd ? s0 : r0;
            u64 h4 = odd ? s1 : r1;
            const u64 o0 = __shfl_xor_sync(0xFFFFFFFFu, h0, 2);
            const u64 o1 = __shfl_xor_sync(0xFFFFFFFFu, h1, 2);
            const u64 o2 = __shfl_xor_sync(0xFFFFFFFFu, h2, 2);
            const u64 o3 = __shfl_xor_sync(0xFFFFFFFFu, h3, 2);
            const u64 o4 = __shfl_xor_sync(0xFFFFFFFFu, h4, 2);
            hp[e2][0] = hig ? o0 : h0;
            hp[e2][1] = hig ? o1 : h1;
            hp[e2][2] = hig ? o2 : h2;
            hp[e2][3] = hig ? o3 : h3;
            hp[e2][4] = hig ? o4 : h4;
            hp[e2][5] = hig ? h0 : o0;
            hp[e2][6] = hig ? h1 : o1;
            hp[e2][7] = hig ? h2 : o2;
            hp[e2][8] = hig ? h3 : o3;
            hp[e2][9] = hig ? h4 : o4;
        }

        // output time-reversed: y_t -> slot (step-1-t); sub0 stores both elements
        if (sub == 0) {
            F2u ya; ya.u = yfin[0];
            F2u yb; yb.u = yfin[1];
            const size_t off = (size_t)(step - 1 - t) * 2;
            *(float2*)(outb0 + off) = ya.f;
            *(float2*)(outb1 + off) = yb.f;
        }
        xp[0] = yfin[0];
        xp[1] = yfin[1];
    }
}

extern "C" void kernel_launch(void* const* d_in, const int* in_sizes, int n_in,
                              void* d_out, int out_size) {
    const float* hidden = (const float*)d_in[0];
    const float* w_ih   = (const float*)d_in[1];
    const float* w_hh   = (const float*)d_in[2];
    const float* b_ih   = (const float*)d_in[3];
    const float* b_hh   = (const float*)d_in[4];
    const float* w_l    = (const float*)d_in[5];
    const float* b_l    = (const float*)d_in[6];

    const int B = in_sizes[0] / HDIM;        // hidden is (1, B, 20)
    const int step = out_size / (2 * B);     // out is (B, step, 2)

    // 4 threads per 2-element group -> 2B threads total
    const long long nthreads = 2LL * B;
    const int grid = (int)((nthreads + TPB - 1) / TPB);
    gru_decoder_kernel<<<grid, TPB>>>(hidden, w_ih, w_hh, b_ih, b_hh, w_l, b_l,
                                      (float*)d_out, B, step);
}

// round 15
// speedup vs baseline: 1.2290x; 1.2290x over previous
#include <cuda_runtime.h>
#include <cuda_bf16.h>
#include <cstdint>

#define HDIM 20
#define TPB 32   // 8 groups of 4 lanes per warp; group handles 2 elements

typedef unsigned long long u64;

union F2u { float2 f; u64 u; };
union F4u { float4 f; u64 u[2]; };

__device__ __forceinline__ u64 pack2(float lo, float hi) {
    F2u t; t.f = make_float2(lo, hi); return t.u;
}
__device__ __forceinline__ float lo2(u64 a) { F2u t; t.u = a; return t.f.x; }
__device__ __forceinline__ float hi2(u64 a) { F2u t; t.u = a; return t.f.y; }

__device__ __forceinline__ u64 fma2(u64 a, u64 b, u64 c) {
    u64 d;
    asm("fma.rn.f32x2 %0, %1, %2, %3;" : "=l"(d) : "l"(a), "l"(b), "l"(c));
    return d;
}
__device__ __forceinline__ u64 mul2(u64 a, u64 b) {
    u64 d;
    asm("mul.rn.f32x2 %0, %1, %2;" : "=l"(d) : "l"(a), "l"(b));
    return d;
}
__device__ __forceinline__ u64 add2(u64 a, u64 b) {
    u64 d;
    asm("add.rn.f32x2 %0, %1, %2;" : "=l"(d) : "l"(a), "l"(b));
    return d;
}
__device__ __forceinline__ float ex2f(float x) {
    float y; asm("ex2.approx.f32 %0, %1;" : "=f"(y) : "f"(x)); return y;
}
__device__ __forceinline__ float rcpf(float x) {
    float y; asm("rcp.approx.f32 %0, %1;" : "=f"(y) : "f"(x)); return y;
}
__device__ __forceinline__ u64 ex2x2(u64 a) { return pack2(ex2f(lo2(a)), ex2f(hi2(a))); }
__device__ __forceinline__ u64 rcp2(u64 a)  { return pack2(rcpf(lo2(a)), rcpf(hi2(a))); }

// pre-scales: sigmoid(v) = rcp(1 + ex2(C1*v)), tanh(v) = 2*rcp(1 + ex2(C2*v)) - 1
#define C1 (-1.4426950408889634f)
#define C2 (-2.8853900817779268f)
#define SIGN2 0x8000000080000000ULL

__global__ __launch_bounds__(TPB, 14)   // cap regs ~146 so all 2048 warps are resident
void gru_decoder_kernel(const float* __restrict__ hidden,
                        const float* __restrict__ w_ih,
                        const float* __restrict__ w_hh,
                        const float* __restrict__ b_ih,
                        const float* __restrict__ b_hh,
                        const float* __restrict__ w_l,
                        const float* __restrict__ b_l,
                        float* __restrict__ out,
                        int B, int step)
{
    // Extended W[i][j]: j<20 -> w_hh[i*20+j], j=20,21 -> w_ih[i*2+(j-20)]
    // Sub-interleaved weights: chunk index ((q*11+jj)*3 + c4), then sub, then 4 floats.
    // A quad's 4 lanes read contiguous 64B per LDS.128 -> conflict-free (1 wavefront).
    // For sub s: pbase = (s>>1)*5 + (s&1)*3, pair P = pbase+q (q < np = 3-(s&1)).
    // The 12 floats (c=4*c4+f) follow the same r/z/n layout as before:
    //   c0..3  = C1*{W[2P][j0], W[2P][j1], W[2P+1][j0], W[2P+1][j1]}    (r)
    //   c4..7  = C1*{W[20+2P][j0], ..., W[21+2P][j1]}                  (z)
    //   c8..11 = C2*{W[40+2P][j0], ..., W[41+2P][j1]}                  (n)
    __shared__ __align__(16) float WQI[3 * 11 * 3 * 4 * 4];   // 6336 B
    __shared__ __align__(16) float BQI[3][4][8];              // biases, sub-interleaved
    __shared__ __align__(16) float WLY[10][4];                // {wl0_j0, wl0_j1, wl1_j0, wl1_j1}
    __shared__ float BL2[2];

    const int tid = threadIdx.x;

    for (int idx = tid; idx < 3 * 11 * 3 * 4 * 4; idx += TPB) {
        const int f   = idx & 3;
        const int sb  = (idx >> 2) & 3;
        const int c4  = (idx >> 4) % 3;
        const int rem = (idx >> 4) / 3;       // q*11 + jj
        const int jj  = rem % 11;
        const int qq  = rem / 11;
        const int pb  = ((sb >> 1) & 1) * 5 + (sb & 1) * 3;
        const int npv = 3 - (sb & 1);
        float val = 0.0f;
        if (qq < npv) {
            const int p = pb + qq;
            const int c = 4 * c4 + f;
            const int g = c >> 2;             // 0=r, 1=z, 2=n
            const int s = c & 3;
            const int row = ((g == 0) ? 2*p : (g == 1) ? 20 + 2*p : 40 + 2*p) + (s >> 1);
            const int j   = ((jj < 10) ? 2*jj : 20) + (s & 1);
            const float w = (j < 20) ? w_hh[row * 20 + j] : w_ih[row * 2 + (j - 20)];
            val = w * ((g == 2) ? C2 : C1);
        }
        WQI[idx] = val;
    }
    for (int idx = tid; idx < 3 * 4 * 8; idx += TPB) {
        const int f  = idx & 7;
        const int sb = (idx >> 3) & 3;
        const int qq = idx >> 5;
        const int pb  = ((sb >> 1) & 1) * 5 + (sb & 1) * 3;
        const int npv = 3 - (sb & 1);
        float val = 0.0f;
        if (qq < npv) {
            const int p = pb + qq;
            switch (f) {
                case 0: val = C1 * (b_ih[2*p]      + b_hh[2*p]);       break;
                case 1: val = C1 * (b_ih[2*p + 1]  + b_hh[2*p + 1]);   break;
                case 2: val = C1 * (b_ih[20 + 2*p] + b_hh[20 + 2*p]);  break;
                case 3: val = C1 * (b_ih[21 + 2*p] + b_hh[21 + 2*p]);  break;
                case 4: val = C2 * b_hh[40 + 2*p];                     break;
                case 5: val = C2 * b_hh[41 + 2*p];                     break;
                case 6: val = C2 * b_ih[40 + 2*p];                     break;
                case 7: val = C2 * b_ih[41 + 2*p];                     break;
            }
        }
        BQI[qq][sb][f] = val;
    }
    if (tid < 10) {
        const int p = tid;
        WLY[p][0] = w_l[2*p];
        WLY[p][1] = w_l[2*p + 1];
        WLY[p][2] = w_l[20 + 2*p];
        WLY[p][3] = w_l[21 + 2*p];
    }
    if (tid < 2) BL2[tid] = b_l[tid];
    __syncthreads();

    const int gtid = blockIdx.x * TPB + tid;
    const int sub  = gtid & 3;                 // role within 4-lane group
    const int gid  = gtid >> 2;                // group id
    const int e0   = gid * 2;                  // group handles elements e0, e0+1
    if (e0 >= B) return;
    const int odd  = sub & 1;                  // odd subs own 2 pairs, even own 3
    const int hig  = (sub >> 1) & 1;           // high subs own pairs 5..9 range
    const int pbase = hig * 5 + odd * 3;       // sub->pbase: 0,3,5,8
    const int np    = 3 - odd;                 // pairs owned: 3,2,3,2

    const float* wbase = WQI + sub * 4;        // this thread's 16B slot

    // register caches for own pairs (x-slot = jj 10; zeros for odd sub q=2 -> unused)
    F4u XRc[3], XZc[3], XNc[3], WLc[3];
#pragma unroll
    for (int q = 0; q < 3; ++q) {
        XRc[q].f = *(const float4*)(wbase + ((q * 11 + 10) * 3 + 0) * 16);
        XZc[q].f = *(const float4*)(wbase + ((q * 11 + 10) * 3 + 1) * 16);
        XNc[q].f = *(const float4*)(wbase + ((q * 11 + 10) * 3 + 2) * 16);
        const int pc = (pbase + q > 9) ? 9 : (pbase + q);
        WLc[q].f = *(const float4*)(&WLY[pc][0]);
    }
    if (odd) { WLc[2].u[0] = 0; WLc[2].u[1] = 0; }   // 3rd pair unused for odd subs
    u64 blu;
    { F2u t; t.f = make_float2(BL2[0], BL2[1]); blu = t.u; }

    // h state (full, both elements): hp[e][jj] = (h[2jj], h[2jj+1])
    u64 hp[2][10];
#pragma unroll
    for (int e2 = 0; e2 < 2; ++e2) {
        const float4* hsrc = (const float4*)(hidden + (size_t)(e0 + e2) * HDIM);
#pragma unroll
        for (int q = 0; q < 5; ++q) {
            float4 v = hsrc[q];
            hp[e2][2*q]     = pack2(v.x, v.y);
            hp[e2][2*q + 1] = pack2(v.z, v.w);
        }
    }

    const u64 ONE2 = pack2(1.0f, 1.0f);
    const u64 TWO2 = pack2(2.0f, 2.0f);
    const u64 NEG1 = pack2(-1.0f, -1.0f);

    u64 xp[2] = {0, 0};
    float* outb0 = out + (size_t)e0 * step * 2;
    float* outb1 = out + (size_t)(e0 + 1) * step * 2;

#pragma unroll 1
    for (int t = 0; t < step; ++t) {
        u64 hn_new[2][3];
        hn_new[0][2] = 0; hn_new[1][2] = 0;    // keep exchange/y math finite for odd subs

#pragma unroll
        for (int q = 0; q < 3; ++q) {
            if (q < np) {
                u64 Ar0[2], Ar1[2], Az0[2], Az1[2], An0[2], An1[2];
                {
                    F4u R, Z, Nw;
                    R.f  = *(const float4*)(wbase + ((q * 11 + 0) * 3 + 0) * 16);
                    Z.f  = *(const float4*)(wbase + ((q * 11 + 0) * 3 + 1) * 16);
                    Nw.f = *(const float4*)(wbase + ((q * 11 + 0) * 3 + 2) * 16);
#pragma unroll
                    for (int e2 = 0; e2 < 2; ++e2) {
                        const u64 h0 = hp[e2][0];
                        Ar0[e2] = mul2(R.u[0],  h0);
                        Ar1[e2] = mul2(R.u[1],  h0);
                        Az0[e2] = mul2(Z.u[0],  h0);
                        Az1[e2] = mul2(Z.u[1],  h0);
                        An0[e2] = mul2(Nw.u[0], h0);
                        An1[e2] = mul2(Nw.u[1], h0);
                    }
                }
#pragma unroll
                for (int jj = 1; jj < 10; ++jj) {
                    F4u R, Z, Nw;
                    R.f  = *(const float4*)(wbase + ((q * 11 + jj) * 3 + 0) * 16);
                    Z.f  = *(const float4*)(wbase + ((q * 11 + jj) * 3 + 1) * 16);
                    Nw.f = *(const float4*)(wbase + ((q * 11 + jj) * 3 + 2) * 16);
#pragma unroll
                    for (int e2 = 0; e2 < 2; ++e2) {
                        const u64 hj = hp[e2][jj];
                        Ar0[e2] = fma2(R.u[0],  hj, Ar0[e2]);
                        Ar1[e2] = fma2(R.u[1],  hj, Ar1[e2]);
                        Az0[e2] = fma2(Z.u[0],  hj, Az0[e2]);
                        Az1[e2] = fma2(Z.u[1],  hj, Az1[e2]);
                        An0[e2] = fma2(Nw.u[0], hj, An0[e2]);
                        An1[e2] = fma2(Nw.u[1], hj, An1[e2]);
                    }
                }

                // x slot (register-cached weights); n's x part separate (inn)
                u64 In0[2], In1[2];
#pragma unroll
                for (int e2 = 0; e2 < 2; ++e2) {
                    const u64 xv = xp[e2];
                    Ar0[e2] = fma2(XRc[q].u[0], xv, Ar0[e2]);
                    Ar1[e2] = fma2(XRc[q].u[1], xv, Ar1[e2]);
                    Az0[e2] = fma2(XZc[q].u[0], xv, Az0[e2]);
                    Az1[e2] = fma2(XZc[q].u[1], xv, Az1[e2]);
                    In0[e2] = mul2(XNc[q].u[0], xv);
                    In1[e2] = mul2(XNc[q].u[1], xv);
                }

                // biases from sub-interleaved smem (conflict-free)
                F4u Brz, Bn;
                Brz.f = *(const float4*)(&BQI[q][sub][0]);
                Bn.f  = *(const float4*)(&BQI[q][sub][4]);

#pragma unroll
                for (int e2 = 0; e2 < 2; ++e2) {
                    const u64 rArg = add2(pack2(lo2(Ar0[e2]) + hi2(Ar0[e2]),
                                                lo2(Ar1[e2]) + hi2(Ar1[e2])), Brz.u[0]);
                    const u64 zArg = add2(pack2(lo2(Az0[e2]) + hi2(Az0[e2]),
                                                lo2(Az1[e2]) + hi2(Az1[e2])), Brz.u[1]);
                    const u64 hnv  = add2(pack2(lo2(An0[e2]) + hi2(An0[e2]),
                                                lo2(An1[e2]) + hi2(An1[e2])), Bn.u[0]);
                    const u64 innv = add2(pack2(lo2(In0[e2]) + hi2(In0[e2]),
                                                lo2(In1[e2]) + hi2(In1[e2])), Bn.u[1]);

                    const u64 rv = rcp2(add2(ex2x2(rArg), ONE2));
                    const u64 zv = rcp2(add2(ex2x2(zArg), ONE2));
                    const u64 s  = fma2(rv, hnv, innv);
                    const u64 nv = fma2(TWO2, rcp2(add2(ex2x2(s), ONE2)), NEG1);

                    const u64 hold = hp[e2][pbase + q];
                    const u64 t1 = fma2(zv, hold, nv);            // z*h + n
                    hn_new[e2][q] = fma2(zv ^ SIGN2, nv, t1);     // (z*h+n) - z*n
                }
            }
        }

        // ---- y partial over own pairs, butterfly-reduced across the 4 lanes ----
        u64 yfin[2];
#pragma unroll
        for (int e2 = 0; e2 < 2; ++e2) {
            u64 Y0 = mul2(WLc[0].u[0], hn_new[e2][0]);
            u64 Y1 = mul2(WLc[0].u[1], hn_new[e2][0]);
            Y0 = fma2(WLc[1].u[0], hn_new[e2][1], Y0);
            Y1 = fma2(WLc[1].u[1], hn_new[e2][1], Y1);
            Y0 = fma2(WLc[2].u[0], hn_new[e2][2], Y0);    // zero-weight for odd subs
            Y1 = fma2(WLc[2].u[1], hn_new[e2][2], Y1);
            u64 ym = pack2(lo2(Y0) + hi2(Y0), lo2(Y1) + hi2(Y1));
            ym = add2(ym, __shfl_xor_sync(0xFFFFFFFFu, ym, 1));
            ym = add2(ym, __shfl_xor_sync(0xFFFFFFFFu, ym, 2));
            yfin[e2] = add2(ym, blu);
        }

        // ---- h exchange: 2-stage butterfly broadcast of all 10 pairs ----
#pragma unroll
        for (int e2 = 0; e2 < 2; ++e2) {
            const u64 s0 = hn_new[e2][0];
            const u64 s1 = hn_new[e2][1];
            const u64 s2 = hn_new[e2][2];
            const u64 r0 = __shfl_xor_sync(0xFFFFFFFFu, s0, 1);
            const u64 r1 = __shfl_xor_sync(0xFFFFFFFFu, s1, 1);
            const u64 r2 = __shfl_xor_sync(0xFFFFFFFFu, s2, 1);
            // assemble own half (pairs 0-4 for subs 0,1; pairs 5-9 for subs 2,3)
            u64 h0 = odd ? r0 : s0;
            u64 h1 = odd ? r1 : s1;
            u64 h2 = odd ? r2 : s2;
            u64 h3 = odd ? s0 : r0;
            u64 h4 = odd ? s1 : r1;
            const u64 o0 = __shfl_xor_sync(0xFFFFFFFFu, h0, 2);
            const u64 o1 = __shfl_xor_sync(0xFFFFFFFFu, h1, 2);
            const u64 o2 = __shfl_xor_sync(0xFFFFFFFFu, h2, 2);
            const u64 o3 = __shfl_xor_sync(0xFFFFFFFFu, h3, 2);
            const u64 o4 = __shfl_xor_sync(0xFFFFFFFFu, h4, 2);
            hp[e2][0] = hig ? o0 : h0;
            hp[e2][1] = hig ? o1 : h1;
            hp[e2][2] = hig ? o2 : h2;
            hp[e2][3] = hig ? o3 : h3;
            hp[e2][4] = hig ? o4 : h4;
            hp[e2][5] = hig ? h0 : o0;
            hp[e2][6] = hig ? h1 : o1;
            hp[e2][7] = hig ? h2 : o2;
            hp[e2][8] = hig ? h3 : o3;
            hp[e2][9] = hig ? h4 : o4;
        }

        // output time-reversed: y_t -> slot (step-1-t); sub0 stores both elements
        if (sub == 0) {
            F2u ya; ya.u = yfin[0];
            F2u yb; yb.u = yfin[1];
            const size_t off = (size_t)(step - 1 - t) * 2;
            *(float2*)(outb0 + off) = ya.f;
            *(float2*)(outb1 + off) = yb.f;
        }
        xp[0] = yfin[0];
        xp[1] = yfin[1];
    }
}

extern "C" void kernel_launch(void* const* d_in, const int* in_sizes, int n_in,
                              void* d_out, int out_size) {
    const float* hidden = (const float*)d_in[0];
    const float* w_ih   = (const float*)d_in[1];
    const float* w_hh   = (const float*)d_in[2];
    const float* b_ih   = (const float*)d_in[3];
    const float* b_hh   = (const float*)d_in[4];
    const float* w_l    = (const float*)d_in[5];
    const float* b_l    = (const float*)d_in[6];

    const int B = in_sizes[0] / HDIM;        // hidden is (1, B, 20)
    const int step = out_size / (2 * B);     // out is (B, step, 2)

    // 4 threads per 2-element group -> 2B threads total
    const long long nthreads = 2LL * B;
    const int grid = (int)((nthreads + TPB - 1) / TPB);
    gru_decoder_kernel<<<grid, TPB>>>(hidden, w_ih, w_hh, b_ih, b_hh, w_l, b_l,
                                      (float*)d_out, B, step);
}

// round 16
// speedup vs baseline: 1.5079x; 1.2269x over previous
#include <cuda_runtime.h>
#include <cuda_bf16.h>
#include <cstdint>

#define HDIM 20
#define TPB 32   // one warp per block; lane parity = role; 2 elements per thread

typedef unsigned long long u64;

union F2u { float2 f; u64 u; };
union F4u { float4 f; u64 u[2]; };

__device__ __forceinline__ u64 pack2(float lo, float hi) {
    F2u t; t.f = make_float2(lo, hi); return t.u;
}
__device__ __forceinline__ float lo2(u64 a) { F2u t; t.u = a; return t.f.x; }
__device__ __forceinline__ float hi2(u64 a) { F2u t; t.u = a; return t.f.y; }

__device__ __forceinline__ u64 fma2(u64 a, u64 b, u64 c) {
    u64 d;
    asm("fma.rn.f32x2 %0, %1, %2, %3;" : "=l"(d) : "l"(a), "l"(b), "l"(c));
    return d;
}
__device__ __forceinline__ u64 mul2(u64 a, u64 b) {
    u64 d;
    asm("mul.rn.f32x2 %0, %1, %2;" : "=l"(d) : "l"(a), "l"(b));
    return d;
}
__device__ __forceinline__ u64 add2(u64 a, u64 b) {
    u64 d;
    asm("add.rn.f32x2 %0, %1, %2;" : "=l"(d) : "l"(a), "l"(b));
    return d;
}
__device__ __forceinline__ float ex2f(float x) {
    float y; asm("ex2.approx.f32 %0, %1;" : "=f"(y) : "f"(x)); return y;
}
__device__ __forceinline__ float rcpf(float x) {
    float y; asm("rcp.approx.f32 %0, %1;" : "=f"(y) : "f"(x)); return y;
}
__device__ __forceinline__ u64 ex2x2(u64 a) { return pack2(ex2f(lo2(a)), ex2f(hi2(a))); }
__device__ __forceinline__ u64 rcp2(u64 a)  { return pack2(rcpf(lo2(a)), rcpf(hi2(a))); }

// pre-scales: sigmoid(v) = rcp(1 + ex2(C1*v)), tanh(v) = 2*rcp(1 + ex2(C2*v)) - 1
#define C1 (-1.4426950408889634f)
#define C2 (-2.8853900817779268f)
#define SIGN2 0x8000000080000000ULL

__global__ __launch_bounds__(TPB, 2)   // allow up to 255 regs; occupancy is grid-limited anyway
void gru_decoder_kernel(const float* __restrict__ hidden,
                        const float* __restrict__ w_ih,
                        const float* __restrict__ w_hh,
                        const float* __restrict__ b_ih,
                        const float* __restrict__ b_hh,
                        const float* __restrict__ w_l,
                        const float* __restrict__ b_l,
                        float* __restrict__ out,
                        int B, int step)
{
    // Extended W[i][j]: j<20 -> w_hh[i*20+j], j=20,21 -> w_ih[i*2+(j-20)]
    // WQ[p][jj][12]: p = gate pair, jj = column pair (jj=10 -> x columns):
    //   c0..3  = C1*{W[2p][j0],    W[2p][j1],    W[2p+1][j0],  W[2p+1][j1]}   (r)
    //   c4..7  = C1*{W[20+2p][j0], W[20+2p][j1], W[21+2p][j0], W[21+2p][j1]}  (z)
    //   c8..11 = C2*{W[40+2p][j0], W[40+2p][j1], W[41+2p][j0], W[41+2p][j1]}  (n)
    // Even/odd lane pbase delta = 5*132 floats = 2640B ≡ 80 (mod 128): bank-disjoint.
    __shared__ __align__(16) float WQ[10][11][12];
    __shared__ __align__(16) float BQ[10][8];   // {br0,br1,bz0,bz1, bhn0,bhn1,bin0,bin1}
    __shared__ __align__(16) float WLY[10][4];  // {wl0_j0, wl0_j1, wl1_j0, wl1_j1}
    __shared__ float BL2[2];

    const int tid = threadIdx.x;

    for (int idx = tid; idx < 10 * 11 * 12; idx += TPB) {
        int p  = idx / 132;
        int r  = idx % 132;
        int jj = r / 12;
        int c  = r % 12;
        int g  = c >> 2;            // 0=r, 1=z, 2=n
        int s  = c & 3;             // bit1 = row offset, bit0 = col offset
        int row = ((g == 0) ? 2*p : (g == 1) ? 20 + 2*p : 40 + 2*p) + (s >> 1);
        int j   = ((jj < 10) ? 2*jj : 20) + (s & 1);
        float w = (j < 20) ? w_hh[row * 20 + j] : w_ih[row * 2 + (j - 20)];
        WQ[p][jj][c] = w * ((g == 2) ? C2 : C1);
    }
    if (tid < 10) {
        int p = tid;
        BQ[p][0] = C1 * (b_ih[2*p]      + b_hh[2*p]);
        BQ[p][1] = C1 * (b_ih[2*p + 1]  + b_hh[2*p + 1]);
        BQ[p][2] = C1 * (b_ih[20 + 2*p] + b_hh[20 + 2*p]);
        BQ[p][3] = C1 * (b_ih[21 + 2*p] + b_hh[21 + 2*p]);
        BQ[p][4] = C2 * b_hh[40 + 2*p];
        BQ[p][5] = C2 * b_hh[41 + 2*p];
        BQ[p][6] = C2 * b_ih[40 + 2*p];
        BQ[p][7] = C2 * b_ih[41 + 2*p];
        WLY[p][0] = w_l[2*p];
        WLY[p][1] = w_l[2*p + 1];
        WLY[p][2] = w_l[20 + 2*p];
        WLY[p][3] = w_l[21 + 2*p];
    }
    if (tid < 2) BL2[tid] = b_l[tid];
    __syncthreads();

    const int gtid = blockIdx.x * TPB + tid;
    const int role = gtid & 1;                 // even lane: pairs 0..4, odd: 5..9
    const int e0   = (gtid & ~1);              // this thread handles elements e0, e0+1
    const int own_off = 5 * role;
    const int oth_off = 5 - own_off;
    const bool valid = (e0 + 1 < B);

    // h state for both elements as natural pairs: hp[e][jj] = (h[2jj], h[2jj+1])
    u64 hp[2][10];
#pragma unroll
    for (int e2 = 0; e2 < 2; ++e2) {
        const int e = valid ? (e0 + e2) : 0;
        const float4* hsrc = (const float4*)(hidden + (size_t)e * HDIM);
#pragma unroll
        for (int q = 0; q < 5; ++q) {
            float4 v = hsrc[q];
            hp[e2][2*q]     = pack2(v.x, v.y);
            hp[e2][2*q + 1] = pack2(v.z, v.w);
        }
    }

    const u64 ONE2 = pack2(1.0f, 1.0f);
    const u64 TWO2 = pack2(2.0f, 2.0f);
    const u64 NEG1 = pack2(-1.0f, -1.0f);

    const float yb0 = role ? 0.0f : BL2[0];
    const float yb1 = role ? 0.0f : BL2[1];

    const float* wqb  = &WQ[own_off][0][0];

    // ---- hoist loop-invariant smem into registers (loaded once, live 200 steps) ----
    F4u BrzC[5], BnC[5];            // biases: 40 regs
    F4u XRc[5], XZc[5], XNc[5];     // x-slot weights: 60 regs
    F4u WLc[5];                     // y weights: 20 regs
#pragma unroll
    for (int q = 0; q < 5; ++q) {
        BrzC[q].f = *(const float4*)(&BQ[own_off + q][0]);
        BnC[q].f  = *(const float4*)(&BQ[own_off + q][4]);
        XRc[q].f  = *(const float4*)(wqb + q * 132 + 120);
        XZc[q].f  = *(const float4*)(wqb + q * 132 + 124);
        XNc[q].f  = *(const float4*)(wqb + q * 132 + 128);
        WLc[q].f  = *(const float4*)(&WLY[own_off + q][0]);
    }

    u64 xp[2] = {0, 0};                        // (x0, x1) pairs per element
    float* outb0 = out + (size_t)e0 * step * 2;
    float* outb1 = out + (size_t)(e0 + 1) * step * 2;

#pragma unroll 1
    for (int t = 0; t < step; ++t) {
        u64 hn_new[2][5];

        // software-pipeline: current-iteration weights live in Rc/Zc/Nc,
        // next iteration's loads issued BEFORE the current fma2 block.
        F4u Rc, Zc, Nc;
        Rc.f = *(const float4*)(wqb + 0);
        Zc.f = *(const float4*)(wqb + 4);
        Nc.f = *(const float4*)(wqb + 8);

#pragma unroll
        for (int q = 0; q < 5; ++q) {
            const float* wq = wqb + q * 132;
            u64 Ar0[2], Ar1[2], Az0[2], Az1[2], An0[2], An1[2];

#pragma unroll
            for (int jj = 0; jj < 10; ++jj) {
                // prefetch next (pair, jj) chunk (compile-time resolved)
                F4u Rn, Zn, Nn;
                const bool has_next = (jj < 9) || (q < 4);
                if (has_next) {
                    const float* nxt = (jj < 9) ? (wq + (jj + 1) * 12)
                                                : (wqb + (q + 1) * 132);
                    Rn.f = *(const float4*)(nxt + 0);
                    Zn.f = *(const float4*)(nxt + 4);
                    Nn.f = *(const float4*)(nxt + 8);
                }

                if (jj == 0) {
#pragma unroll
                    for (int e2 = 0; e2 < 2; ++e2) {
                        const u64 h0 = hp[e2][0];
                        Ar0[e2] = mul2(Rc.u[0], h0);
                        Ar1[e2] = mul2(Rc.u[1], h0);
                        Az0[e2] = mul2(Zc.u[0], h0);
                        Az1[e2] = mul2(Zc.u[1], h0);
                        An0[e2] = mul2(Nc.u[0], h0);
                        An1[e2] = mul2(Nc.u[1], h0);
                    }
                } else {
#pragma unroll
                    for (int e2 = 0; e2 < 2; ++e2) {
                        const u64 hj = hp[e2][jj];
                        Ar0[e2] = fma2(Rc.u[0], hj, Ar0[e2]);
                        Ar1[e2] = fma2(Rc.u[1], hj, Ar1[e2]);
                        Az0[e2] = fma2(Zc.u[0], hj, Az0[e2]);
                        Az1[e2] = fma2(Zc.u[1], hj, Az1[e2]);
                        An0[e2] = fma2(Nc.u[0], hj, An0[e2]);
                        An1[e2] = fma2(Nc.u[1], hj, An1[e2]);
                    }
                }

                if (has_next) { Rc = Rn; Zc = Zn; Nc = Nn; }  // renamed, no MOV
            }

            // x slot (register-cached weights); n's x part separate (inn)
            u64 In0[2], In1[2];
#pragma unroll
            for (int e2 = 0; e2 < 2; ++e2) {
                const u64 xv = xp[e2];
                Ar0[e2] = fma2(XRc[q].u[0], xv, Ar0[e2]);
                Ar1[e2] = fma2(XRc[q].u[1], xv, Ar1[e2]);
                Az0[e2] = fma2(XZc[q].u[0], xv, Az0[e2]);
                Az1[e2] = fma2(XZc[q].u[1], xv, Az1[e2]);
                In0[e2] = mul2(XNc[q].u[0], xv);
                In1[e2] = mul2(XNc[q].u[1], xv);
            }

#pragma unroll
            for (int e2 = 0; e2 < 2; ++e2) {
                const u64 rArg = add2(pack2(lo2(Ar0[e2]) + hi2(Ar0[e2]),
                                            lo2(Ar1[e2]) + hi2(Ar1[e2])), BrzC[q].u[0]);
                const u64 zArg = add2(pack2(lo2(Az0[e2]) + hi2(Az0[e2]),
                                            lo2(Az1[e2]) + hi2(Az1[e2])), BrzC[q].u[1]);
                const u64 hnv  = add2(pack2(lo2(An0[e2]) + hi2(An0[e2]),
                                            lo2(An1[e2]) + hi2(An1[e2])), BnC[q].u[0]);
                const u64 innv = add2(pack2(lo2(In0[e2]) + hi2(In0[e2]),
                                            lo2(In1[e2]) + hi2(In1[e2])), BnC[q].u[1]);

                const u64 rv = rcp2(add2(ex2x2(rArg), ONE2));
                const u64 zv = rcp2(add2(ex2x2(zArg), ONE2));
                const u64 s  = fma2(rv, hnv, innv);
                const u64 nv = fma2(TWO2, rcp2(add2(ex2x2(s), ONE2)), NEG1);

                const u64 hold = hp[e2][own_off + q];
                const u64 t1 = fma2(zv, hold, nv);            // z*h + n
                hn_new[e2][q] = fma2(zv ^ SIGN2, nv, t1);     // (z*h+n) - z*n
            }
        }

        // partial y over own 10 dims for both elements (register-cached weights)
        u64 Y0[2], Y1[2];
#pragma unroll
        for (int e2 = 0; e2 < 2; ++e2) {
            Y0[e2] = mul2(WLc[0].u[0], hn_new[e2][0]);
            Y1[e2] = mul2(WLc[0].u[1], hn_new[e2][0]);
        }
#pragma unroll
        for (int q = 1; q < 5; ++q) {
#pragma unroll
            for (int e2 = 0; e2 < 2; ++e2) {
                Y0[e2] = fma2(WLc[q].u[0], hn_new[e2][q], Y0[e2]);
                Y1[e2] = fma2(WLc[q].u[1], hn_new[e2][q], Y1[e2]);
            }
        }

        u64 yfull[2];
#pragma unroll
        for (int e2 = 0; e2 < 2; ++e2) {
            const float y0p = lo2(Y0[e2]) + hi2(Y0[e2]) + yb0;
            const float y1p = lo2(Y1[e2]) + hi2(Y1[e2]) + yb1;
            u64 ym = pack2(y0p, y1p);
            u64 yo = __shfl_xor_sync(0xFFFFFFFFu, ym, 1);
            yfull[e2] = add2(ym, yo);          // both lanes now hold full y
        }

        // exchange h halves with partner lane, update state
#pragma unroll
        for (int q = 0; q < 5; ++q) {
#pragma unroll
            for (int e2 = 0; e2 < 2; ++e2) {
                const u64 pq = __shfl_xor_sync(0xFFFFFFFFu, hn_new[e2][q], 1);
                hp[e2][own_off + q] = hn_new[e2][q];
                hp[e2][oth_off + q] = pq;
            }
        }

        // output time-reversed: y_t -> slot (step-1-t); even lane stores both
        if (!role && valid) {
            F2u ya; ya.u = yfull[0];
            F2u yb; yb.u = yfull[1];
            const size_t off = (size_t)(step - 1 - t) * 2;
            *(float2*)(outb0 + off) = ya.f;
            *(float2*)(outb1 + off) = yb.f;
        }
        xp[0] = yfull[0];
        xp[1] = yfull[1];
    }
}

extern "C" void kernel_launch(void* const* d_in, const int* in_sizes, int n_in,
                              void* d_out, int out_size) {
    const float* hidden = (const float*)d_in[0];
    const float* w_ih   = (const float*)d_in[1];
    const float* w_hh   = (const float*)d_in[2];
    const float* b_ih   = (const float*)d_in[3];
    const float* b_hh   = (const float*)d_in[4];
    const float* w_l    = (const float*)d_in[5];
    const float* b_l    = (const float*)d_in[6];

    const int B = in_sizes[0] / HDIM;        // hidden is (1, B, 20)
    const int step = out_size / (2 * B);     // out is (B, step, 2)

    // threads = B total (2 threads per element-pair, 2 elements per thread)
    const int nthreads = B;
    const int grid = (nthreads + TPB - 1) / TPB;
    gru_decoder_kernel<<<grid, TPB>>>(hidden, w_ih, w_hh, b_ih, b_hh, w_l, b_l,
                                      (float*)d_out, B, step);
}